// round 5
// baseline (speedup 1.0000x reference)
#include <cuda_runtime.h>

#define NN 50000
#define EE 800000

// ---- scratch (static device arrays; no allocation) ----
__device__ __align__(256) float d_g[NN * 64];   // folded node projection g[n][h*8+k]
__device__ __align__(256) float d_Wg[64 * 128]; // W_att folded into W
__device__ __align__(256) float d_Wc8[128];     // 8 * (W_edge_att @ W_edge)  [8][16]
__device__ __align__(256) float d_S[NN * 8];    // per-node, per-head sum of exp
__device__ __align__(256) float d_Z[8];         // global per-head softmax denominator
__device__ int d_is64;                          // 1 if edge_index is int64, 0 if int32

#define ZERO_BLOCKS 1563   // ceil(NN*8/256)
#define PREP_BLOCKS 33

// ---------------------------------------------------------------------------
// Fused: zero S/Z + fold small weights + detect edge_index dtype.
__global__ void prep_all_kernel(const float* __restrict__ W,
                                const float* __restrict__ W_edge,
                                const float* __restrict__ W_edge_att,
                                const float* __restrict__ W_att,
                                const int* __restrict__ ei_words) {
    int b = blockIdx.x;
    int t = threadIdx.x;
    if (b < ZERO_BLOCKS) {
        int i = b * 256 + t;
        if (i < NN * 8) d_S[i] = 0.f;
        if (b == 0 && t < 8) d_Z[t] = 0.f;
    } else if (b < ZERO_BLOCKS + PREP_BLOCKS) {
        int i = (b - ZERO_BLOCKS) * 256 + t;
        if (i < 64 * 128) {
            int j = i >> 7, c = i & 127;
            int hh = j >> 3, k = j & 7;
            float acc = 0.f;
#pragma unroll
            for (int d = 0; d < 8; d++)
                acc += W_att[k * 8 + d] * W[(hh * 8 + d) * 128 + c];
            d_Wg[i] = acc;
        } else if (i < 64 * 128 + 128) {
            int ii = i - 64 * 128;
            int h = ii >> 4, q = ii & 15;
            float acc = 0.f;
            for (int m = 0; m < 64; m++)
                acc += W_edge_att[h * 64 + m] * W_edge[m * 16 + q];
            d_Wc8[ii] = 8.0f * acc;   // edge_term = ea * D, D folded here
        }
    } else {
        // dtype detect: int64 little-endian values < 2^31 -> odd words all 0
        int w = ei_words[2 * t + 1];
        unsigned any = __ballot_sync(0xffffffffu, w != 0);
        __shared__ int nz;
        if (t == 0) nz = 0;
        __syncthreads();
        if ((t & 31) == 0 && any) atomicOr(&nz, 1);
        __syncthreads();
        if (t == 0) d_is64 = nz ? 0 : 1;
    }
}

// ---------------------------------------------------------------------------
// g = x @ Wg.T : [N,128] x [128,64] -> [N,64]
// 128x64 tile per block (256 threads), 8x4 micro-tile computed as 4x4 f32x2
// pairs via fma.rn.f32x2 (packed dual-fp32 FMA). xs stored k-major so an
// LDS.64 yields two consecutive M-rows; ws stored duplicated so an LDS.64
// yields {w,w}.
__global__ void __launch_bounds__(256) gemm_g_kernel(const float* __restrict__ x,
                                                     int n) {
    __shared__ float xs_t[32 * 130];            // [k][m], stride 130 (float2-aligned)
    __shared__ float2 ws2[32 * 65];             // [k][s], duplicated, stride 65
    int t = threadIdx.x;
    int tx = t & 15, ty = t >> 4;
    int n0 = blockIdx.x * 128;

    unsigned long long acc2[4][4];
#pragma unroll
    for (int r = 0; r < 4; r++)
#pragma unroll
        for (int s = 0; s < 4; s++) acc2[r][s] = 0ull;

    for (int kc = 0; kc < 128; kc += 32) {
#pragma unroll
        for (int i = 0; i < 4; i++) {           // 1024 float4 = 128 rows x 8 kq
            int idx = t + i * 256;
            int m = idx >> 3;
            int kq = idx & 7;
            float4 v = make_float4(0.f, 0.f, 0.f, 0.f);
            if (n0 + m < n)
                v = *reinterpret_cast<const float4*>(
                        x + (size_t)(n0 + m) * 128 + kc + kq * 4);
            xs_t[(kq * 4 + 0) * 130 + m] = v.x;
            xs_t[(kq * 4 + 1) * 130 + m] = v.y;
            xs_t[(kq * 4 + 2) * 130 + m] = v.z;
            xs_t[(kq * 4 + 3) * 130 + m] = v.w;
        }
#pragma unroll
        for (int i = 0; i < 2; i++) {           // 512 float4 = 64 cols x 8 kq
            int idx = t + i * 256;
            int m = idx >> 3;
            int kq = idx & 7;
            float4 w = *reinterpret_cast<const float4*>(
                    d_Wg + m * 128 + kc + kq * 4);
            ws2[(kq * 4 + 0) * 65 + m] = make_float2(w.x, w.x);
            ws2[(kq * 4 + 1) * 65 + m] = make_float2(w.y, w.y);
            ws2[(kq * 4 + 2) * 65 + m] = make_float2(w.z, w.z);
            ws2[(kq * 4 + 3) * 65 + m] = make_float2(w.w, w.w);
        }
        __syncthreads();
#pragma unroll 8
        for (int k = 0; k < 32; k++) {
            unsigned long long b2[4], a2[4];
#pragma unroll
            for (int s = 0; s < 4; s++)
                b2[s] = *reinterpret_cast<const unsigned long long*>(
                        &ws2[k * 65 + tx + 16 * s]);
#pragma unroll
            for (int r = 0; r < 4; r++)
                a2[r] = *reinterpret_cast<const unsigned long long*>(
                        &xs_t[k * 130 + ty * 8 + 2 * r]);
#pragma unroll
            for (int r = 0; r < 4; r++)
#pragma unroll
                for (int s = 0; s < 4; s++)
                    asm("fma.rn.f32x2 %0, %1, %2, %0;"
                        : "+l"(acc2[r][s]) : "l"(a2[r]), "l"(b2[s]));
        }
        __syncthreads();
    }
#pragma unroll
    for (int r = 0; r < 4; r++) {
#pragma unroll
        for (int s = 0; s < 4; s++) {
            float2 v = *reinterpret_cast<const float2*>(&acc2[r][s]);
            int m0 = n0 + ty * 8 + 2 * r;
            if (m0 < n)     d_g[(size_t)m0 * 64 + tx + 16 * s] = v.x;
            if (m0 + 1 < n) d_g[(size_t)(m0 + 1) * 64 + tx + 16 * s] = v.y;
        }
    }
}

// ---------------------------------------------------------------------------
// Edge pass, head-per-thread: 8 threads per edge (one per head), 32 edges per
// 256-thread block tile, grid-stride over tiles.
__global__ void __launch_bounds__(256) edge_kernel(const float* __restrict__ edge_attr,
                                                   const void* __restrict__ eidx,
                                                   int E) {
    __shared__ float sA[32 * 17];
    __shared__ float sred[8][8];
    int t = threadIdx.x;
    int grp = t >> 3, h = t & 7;
    int is64 = d_is64;

    float wc[16];
#pragma unroll
    for (int q = 0; q < 16; q++) wc[q] = d_Wc8[h * 16 + q];

    float zacc = 0.f;
    int ntiles = (E + 31) >> 5;
    for (int tile = blockIdx.x; tile < ntiles; tile += gridDim.x) {
        int base = tile << 5;
        __syncthreads();                      // protect smem reuse
        {
            int idx = 2 * t;                  // float offset within tile
            int e = idx >> 4, q = idx & 15;
            float2 v = make_float2(0.f, 0.f);
            if (base + e < E)
                v = *reinterpret_cast<const float2*>(
                        edge_attr + (size_t)(base + e) * 16 + q);
            sA[e * 17 + q] = v.x;
            sA[e * 17 + q + 1] = v.y;
        }
        __syncthreads();

        int e = base + grp;
        float p = 0.f;
        if (e < E) {
            int s, d;
            if (is64) {
                const long long* ei = (const long long*)eidx;
                s = (int)ei[e];
                d = (int)ei[E + e];
            } else {
                const int* ei = (const int*)eidx;
                s = ei[e];
                d = ei[E + e];
            }
            const float4* gs =
                reinterpret_cast<const float4*>(d_g + (size_t)s * 64 + h * 8);
            const float4* gd =
                reinterpret_cast<const float4*>(d_g + (size_t)d * 64 + h * 8);
            float4 a0 = gs[0], a1 = gs[1];
            float4 b0 = gd[0], b1 = gd[1];
            const float* ap = sA + grp * 17;
            float a = 0.f;
#pragma unroll
            for (int q = 0; q < 16; q++) a = fmaf(wc[q], ap[q], a);
            a += a0.x * b0.x + a0.y * b0.y + a0.z * b0.z + a0.w * b0.w
               + a1.x * b1.x + a1.y * b1.y + a1.z * b1.z + a1.w * b1.w;
            a = a > 0.f ? a : 0.2f * a;       // leaky_relu(0.2)
            p = __expf(a);
            atomicAdd(d_S + (size_t)d * 8 + h, p);
        }
        zacc += p;
    }

    // Z reduction: sum over lanes with the same head within the warp
    zacc += __shfl_xor_sync(0xffffffffu, zacc, 8);
    zacc += __shfl_xor_sync(0xffffffffu, zacc, 16);
    int lane = t & 31, wid = t >> 5;
    __syncthreads();
    if (lane < 8) sred[wid][lane] = zacc;
    __syncthreads();
    if (t < 8) {
        float z = 0.f;
#pragma unroll
        for (int w = 0; w < 8; w++) z += sred[w][t];
        atomicAdd(&d_Z[t], z);
    }
}

// ---------------------------------------------------------------------------
// out[v] = relu( W_out @ (g[v] * S[v,h]/Z[h]) )
// 4 threads per node, split over the 64-dim K axis; Wout staged in smem
// (transposed); invZ computed once per block; shfl reduction.
__global__ void __launch_bounds__(256) out_kernel(const float* __restrict__ Wout,
                                                  float* __restrict__ out, int n) {
    __shared__ float swout[64][9];    // [k][i], padded
    __shared__ float sinvZ[8];
    int t = threadIdx.x;
#pragma unroll
    for (int i = 0; i < 2; i++) {
        int idx = t + i * 256;        // 512 = 8 rows x 64 cols
        int row = idx >> 6, k = idx & 63;
        swout[k][row] = Wout[row * 64 + k];
    }
    if (t < 8) sinvZ[t] = __frcp_rn(d_Z[t]);
    __syncthreads();

    int gid = blockIdx.x * 64 + (t >> 2);   // node handled by this 4-group
    int sub = t & 3;
    if (gid >= n) return;

    // per-head scale factors
    float t8[8];
    const float4* Sp = reinterpret_cast<const float4*>(d_S + (size_t)gid * 8);
    float4 s0 = Sp[0], s1 = Sp[1];
    t8[0] = s0.x * sinvZ[0]; t8[1] = s0.y * sinvZ[1];
    t8[2] = s0.z * sinvZ[2]; t8[3] = s0.w * sinvZ[3];
    t8[4] = s1.x * sinvZ[4]; t8[5] = s1.y * sinvZ[5];
    t8[6] = s1.z * sinvZ[6]; t8[7] = s1.w * sinvZ[7];

    float acc[8];
#pragma unroll
    for (int i = 0; i < 8; i++) acc[i] = 0.f;

    const float4* g4 = reinterpret_cast<const float4*>(d_g + (size_t)gid * 64);
#pragma unroll
    for (int j = 0; j < 4; j++) {
        int q = sub * 4 + j;                 // float4 index 0..15
        float4 gv = g4[q];
        float tt = t8[q >> 1];
        gv.x *= tt; gv.y *= tt; gv.z *= tt; gv.w *= tt;
        int k0 = q * 4;
#pragma unroll
        for (int i = 0; i < 8; i++) {
            acc[i] = fmaf(gv.x, swout[k0 + 0][i],
                     fmaf(gv.y, swout[k0 + 1][i],
                     fmaf(gv.z, swout[k0 + 2][i],
                     fmaf(gv.w, swout[k0 + 3][i], acc[i]))));
        }
    }
#pragma unroll
    for (int i = 0; i < 8; i++) {
        acc[i] += __shfl_xor_sync(0xffffffffu, acc[i], 1);
        acc[i] += __shfl_xor_sync(0xffffffffu, acc[i], 2);
    }
    if (sub == 0) {
        float4 o0 = make_float4(fmaxf(acc[0], 0.f), fmaxf(acc[1], 0.f),
                                fmaxf(acc[2], 0.f), fmaxf(acc[3], 0.f));
        float4 o1 = make_float4(fmaxf(acc[4], 0.f), fmaxf(acc[5], 0.f),
                                fmaxf(acc[6], 0.f), fmaxf(acc[7], 0.f));
        float4* op = reinterpret_cast<float4*>(out + (size_t)gid * 8);
        op[0] = o0;
        op[1] = o1;
    }
}

// ---------------------------------------------------------------------------
extern "C" void kernel_launch(void* const* d_in, const int* in_sizes, int n_in,
                              void* d_out, int out_size) {
    const float* x          = (const float*)d_in[0];
    const float* edge_attr  = (const float*)d_in[1];
    const float* W          = (const float*)d_in[2];
    const float* W_edge     = (const float*)d_in[3];
    const float* W_edge_att = (const float*)d_in[4];
    const float* W_att      = (const float*)d_in[5];
    const float* W_out      = (const float*)d_in[6];
    const void*  eidx       = (const void*)d_in[7];
    int N = in_sizes[0] / 128;   // 50000
    int E = in_sizes[7] / 2;     // 800000

    prep_all_kernel<<<ZERO_BLOCKS + PREP_BLOCKS + 1, 256>>>(
        W, W_edge, W_edge_att, W_att, (const int*)eidx);
    gemm_g_kernel<<<(N + 127) / 128, 256>>>(x, N);
    edge_kernel<<<1184, 256>>>(edge_attr, eidx, E);
    out_kernel<<<(N + 63) / 64, 256>>>(W_out, (float*)d_out, N);
}

// round 8
// speedup vs baseline: 1.8764x; 1.8764x over previous
#include <cuda_runtime.h>

#define NN 50000
#define EE 800000

// ---- scratch (static device arrays; no allocation) ----
__device__ __align__(256) float d_g[NN * 64];   // folded node projection g[n][h*8+k]
__device__ __align__(256) float d_Wg[64 * 128]; // W_att folded into W
__device__ __align__(256) float d_Wc8[128];     // 8 * (W_edge_att @ W_edge)  [8][16]
__device__ __align__(256) float d_S[NN * 8];    // per-node, per-head sum of exp
__device__ __align__(256) float d_Z[8];         // global per-head softmax denominator
__device__ int d_is64;                          // 1 if edge_index is int64, 0 if int32

#define ZERO_BLOCKS 1563   // ceil(NN*8/256)
#define PREP_BLOCKS 33

// ---------------------------------------------------------------------------
// Fused: zero S/Z + fold small weights + detect edge_index dtype.
__global__ void prep_all_kernel(const float* __restrict__ W,
                                const float* __restrict__ W_edge,
                                const float* __restrict__ W_edge_att,
                                const float* __restrict__ W_att,
                                const int* __restrict__ ei_words) {
    int b = blockIdx.x;
    int t = threadIdx.x;
    if (b < ZERO_BLOCKS) {
        int i = b * 256 + t;
        if (i < NN * 8) d_S[i] = 0.f;
        if (b == 0 && t < 8) d_Z[t] = 0.f;
    } else if (b < ZERO_BLOCKS + PREP_BLOCKS) {
        int i = (b - ZERO_BLOCKS) * 256 + t;
        if (i < 64 * 128) {
            int j = i >> 7, c = i & 127;
            int hh = j >> 3, k = j & 7;
            float acc = 0.f;
#pragma unroll
            for (int d = 0; d < 8; d++)
                acc += W_att[k * 8 + d] * W[(hh * 8 + d) * 128 + c];
            d_Wg[i] = acc;
        } else if (i < 64 * 128 + 128) {
            int ii = i - 64 * 128;
            int h = ii >> 4, q = ii & 15;
            float acc = 0.f;
            for (int m = 0; m < 64; m++)
                acc += W_edge_att[h * 64 + m] * W_edge[m * 16 + q];
            d_Wc8[ii] = 8.0f * acc;   // edge_term = ea * D, D folded here
        }
    } else {
        // dtype detect: int64 little-endian values < 2^31 -> odd words all 0
        int w = ei_words[2 * t + 1];
        unsigned any = __ballot_sync(0xffffffffu, w != 0);
        __shared__ int nz;
        if (t == 0) nz = 0;
        __syncthreads();
        if ((t & 31) == 0 && any) atomicOr(&nz, 1);
        __syncthreads();
        if (t == 0) d_is64 = nz ? 0 : 1;
    }
}

// ---------------------------------------------------------------------------
// g = x @ Wg.T : [N,128] x [128,64] -> [N,64]
// 128x64 tile per block (256 threads), 8x4 register micro-tile, K-chunks of 32.
// (R4 version — known good.)
__global__ void __launch_bounds__(256) gemm_g_kernel(const float* __restrict__ x,
                                                     int n) {
    __shared__ float xs[128][36];
    __shared__ float ws[64][36];
    int t = threadIdx.x;
    int tx = t & 15, ty = t >> 4;
    int n0 = blockIdx.x * 128;
    float acc[8][4];
#pragma unroll
    for (int r = 0; r < 8; r++)
#pragma unroll
        for (int s = 0; s < 4; s++) acc[r][s] = 0.f;

    for (int kc = 0; kc < 128; kc += 32) {
#pragma unroll
        for (int i = 0; i < 4; i++) {        // 1024 float4 = 128 rows x 8
            int idx = t + i * 256;
            int m = idx >> 3;
            int kq = idx & 7;
            float4 v = make_float4(0.f, 0.f, 0.f, 0.f);
            if (n0 + m < n)
                v = *reinterpret_cast<const float4*>(
                        x + (size_t)(n0 + m) * 128 + kc + kq * 4);
            *reinterpret_cast<float4*>(&xs[m][kq * 4]) = v;
        }
#pragma unroll
        for (int i = 0; i < 2; i++) {        // 512 float4 = 64 rows x 8
            int idx = t + i * 256;
            int m = idx >> 3;
            int kq = idx & 7;
            float4 w = *reinterpret_cast<const float4*>(
                    d_Wg + m * 128 + kc + kq * 4);
            *reinterpret_cast<float4*>(&ws[m][kq * 4]) = w;
        }
        __syncthreads();
#pragma unroll
        for (int k4 = 0; k4 < 8; k4++) {
            float4 b[4];
#pragma unroll
            for (int s = 0; s < 4; s++)
                b[s] = *reinterpret_cast<const float4*>(&ws[tx + 16 * s][k4 * 4]);
#pragma unroll
            for (int r = 0; r < 8; r++) {
                float4 a = *reinterpret_cast<const float4*>(&xs[ty * 8 + r][k4 * 4]);
#pragma unroll
                for (int s = 0; s < 4; s++)
                    acc[r][s] += a.x * b[s].x + a.y * b[s].y +
                                 a.z * b[s].z + a.w * b[s].w;
            }
        }
        __syncthreads();
    }
#pragma unroll
    for (int r = 0; r < 8; r++) {
        int m = n0 + ty * 8 + r;
        if (m < n) {
#pragma unroll
            for (int s = 0; s < 4; s++)
                d_g[(size_t)m * 64 + tx + 16 * s] = acc[r][s];
        }
    }
}

// ---------------------------------------------------------------------------
// Edge pass, head-per-thread, 64-edge tiles, 2 edges per 8-thread group.
// Indices staged in smem (kills 8x-redundant index loads); edge_attr staged
// with stride-20 aligned float4 stores; per-group broadcast reads.
__global__ void __launch_bounds__(256) edge_kernel(const float* __restrict__ edge_attr,
                                                   const void* __restrict__ eidx,
                                                   int E) {
    __shared__ float sA[64 * 20];    // [edge][attr], stride 20
    __shared__ int sidx[128];        // src[0..63], dst[64..127]
    __shared__ float sred[8][8];
    int t = threadIdx.x;
    int grp = t >> 3, h = t & 7;
    int is64 = d_is64;

    float wc[16];
#pragma unroll
    for (int q = 0; q < 16; q++) wc[q] = d_Wc8[h * 16 + q];

    float zacc = 0.f;
    int ntiles = (E + 63) >> 6;
    for (int tile = blockIdx.x; tile < ntiles; tile += gridDim.x) {
        int base = tile << 6;
        __syncthreads();                      // protect smem reuse
        {
            int e = t >> 2, q4 = t & 3;       // 64 edges x 4 quarters
            float4 v = make_float4(0.f, 0.f, 0.f, 0.f);
            if (base + e < E)
                v = *reinterpret_cast<const float4*>(
                        edge_attr + (size_t)(base + e) * 16 + q4 * 4);
            *reinterpret_cast<float4*>(&sA[e * 20 + q4 * 4]) = v;
        }
        if (t < 128) {
            int e = t & 63, half = t >> 6;    // 0 = src, 1 = dst
            int v = 0;
            int ge = base + e;
            if (ge < E)
                v = is64 ? (int)((const long long*)eidx)[(size_t)half * E + ge]
                         : ((const int*)eidx)[(size_t)half * E + ge];
            sidx[half * 64 + e] = v;
        }
        __syncthreads();

#pragma unroll
        for (int u = 0; u < 2; u++) {
            int el = grp + u * 32;
            int e = base + el;
            float p = 0.f;
            if (e < E) {
                int s = sidx[el], d = sidx[64 + el];
                const float4* gs =
                    reinterpret_cast<const float4*>(d_g + (size_t)s * 64 + h * 8);
                const float4* gd =
                    reinterpret_cast<const float4*>(d_g + (size_t)d * 64 + h * 8);
                float4 a0 = gs[0], a1 = gs[1];
                float4 b0 = gd[0], b1 = gd[1];
                const float* ap = sA + el * 20;
                float a = 0.f;
#pragma unroll
                for (int q = 0; q < 16; q++) a = fmaf(wc[q], ap[q], a);
                a += a0.x * b0.x + a0.y * b0.y + a0.z * b0.z + a0.w * b0.w
                   + a1.x * b1.x + a1.y * b1.y + a1.z * b1.z + a1.w * b1.w;
                a = a > 0.f ? a : 0.2f * a;   // leaky_relu(0.2)
                p = __expf(a);
                atomicAdd(d_S + (size_t)d * 8 + h, p);
            }
            zacc += p;
        }
    }

    // Z reduction: sum over lanes with the same head within the warp
    zacc += __shfl_xor_sync(0xffffffffu, zacc, 8);
    zacc += __shfl_xor_sync(0xffffffffu, zacc, 16);
    int lane = t & 31, wid = t >> 5;
    __syncthreads();
    if (lane < 8) sred[wid][lane] = zacc;
    __syncthreads();
    if (t < 8) {
        float z = 0.f;
#pragma unroll
        for (int w = 0; w < 8; w++) z += sred[w][t];
        atomicAdd(&d_Z[t], z);
    }
}

// ---------------------------------------------------------------------------
// out[v] = relu( W_out @ (g[v] * S[v,h]/Z[h]) )  (R4 shape, block=128,
// block-shared invZ instead of per-thread divides)
__global__ void __launch_bounds__(128) out_kernel(const float* __restrict__ Wout,
                                                  float* __restrict__ out, int n) {
    __shared__ float sinvZ[8];
    int t = threadIdx.x;
    if (t < 8) sinvZ[t] = __frcp_rn(d_Z[t]);
    __syncthreads();
    int v = blockIdx.x * blockDim.x + t;
    if (v >= n) return;
    float t8[8];
    const float* Sp = d_S + (size_t)v * 8;
#pragma unroll
    for (int h = 0; h < 8; h++) t8[h] = Sp[h] * sinvZ[h];
    float acc[8];
#pragma unroll
    for (int i = 0; i < 8; i++) acc[i] = 0.f;
    const float4* g4 = reinterpret_cast<const float4*>(d_g + (size_t)v * 64);
#pragma unroll
    for (int jq = 0; jq < 16; jq++) {
        float4 gv = g4[jq];
        float tt = t8[jq >> 1];
        gv.x *= tt; gv.y *= tt; gv.z *= tt; gv.w *= tt;
#pragma unroll
        for (int i = 0; i < 8; i++) {
            float4 w = *reinterpret_cast<const float4*>(Wout + i * 64 + jq * 4);
            acc[i] += gv.x * w.x + gv.y * w.y + gv.z * w.z + gv.w * w.w;
        }
    }
#pragma unroll
    for (int i = 0; i < 8; i++)
        out[(size_t)v * 8 + i] = fmaxf(acc[i], 0.f);
}

// ---------------------------------------------------------------------------
extern "C" void kernel_launch(void* const* d_in, const int* in_sizes, int n_in,
                              void* d_out, int out_size) {
    const float* x          = (const float*)d_in[0];
    const float* edge_attr  = (const float*)d_in[1];
    const float* W          = (const float*)d_in[2];
    const float* W_edge     = (const float*)d_in[3];
    const float* W_edge_att = (const float*)d_in[4];
    const float* W_att      = (const float*)d_in[5];
    const float* W_out      = (const float*)d_in[6];
    const void*  eidx       = (const void*)d_in[7];
    int N = in_sizes[0] / 128;   // 50000
    int E = in_sizes[7] / 2;     // 800000

    prep_all_kernel<<<ZERO_BLOCKS + PREP_BLOCKS + 1, 256>>>(
        W, W_edge, W_edge_att, W_att, (const int*)eidx);
    gemm_g_kernel<<<(N + 127) / 128, 256>>>(x, N);
    edge_kernel<<<1184, 256>>>(edge_attr, eidx, E);
    out_kernel<<<(N + 127) / 128, 128>>>(W_out, (float*)d_out, N);
}